// round 7
// baseline (speedup 1.0000x reference)
#include <cuda_runtime.h>
#include <cuda_fp16.h>
#include <math.h>

#define NB   64
#define NT   512
#define NIN  512
#define NH   1024
#define NH3  3072
#define GCTA 128

__device__ __half2  g_x16[NB * NT * NIN / 2];
__device__ __half2  g_w16[NH3 * NIN / 2];
__device__ __half2  g_gi0[(size_t)NB * NT * NH3 / 2];  // [t][b][3072] fp16, +bias
__device__ __half2  g_h0[2][NB * NH / 2];
__device__ __half2  g_h1[2][NB * NH / 2];
__device__ unsigned g_bar0, g_bar1, g_bari;

__device__ __forceinline__ float sigm(float x) { return 1.0f / (1.0f + __expf(-x)); }

__device__ __forceinline__ void mma16816(float* c, unsigned a0, unsigned a1,
                                         unsigned a2, unsigned a3,
                                         unsigned b0, unsigned b1) {
    asm volatile(
        "mma.sync.aligned.m16n8k16.row.col.f32.f16.f16.f32 "
        "{%0,%1,%2,%3},{%4,%5,%6,%7},{%8,%9},{%0,%1,%2,%3};\n"
        : "+f"(c[0]), "+f"(c[1]), "+f"(c[2]), "+f"(c[3])
        : "r"(a0), "r"(a1), "r"(a2), "r"(a3), "r"(b0), "r"(b1));
}

__device__ __forceinline__ void cp16(unsigned dst, const void* src) {
    asm volatile("cp.async.cg.shared.global [%0], [%1], 16;" :: "r"(dst), "l"(src));
}
__device__ __forceinline__ void cp_commit() { asm volatile("cp.async.commit_group;"); }
template <int N> __device__ __forceinline__ void cp_wait() {
    asm volatile("cp.async.wait_group %0;" :: "n"(N));
}

__device__ __forceinline__ void bar_arrive(unsigned* bar) {
    __syncthreads();
    if (threadIdx.x == 0) { __threadfence(); atomicAdd(bar, 1u); }
}
__device__ __forceinline__ void bar_wait(unsigned* bar, unsigned target) {
    if (threadIdx.x == 0) {
        unsigned v;
        do {
            asm volatile("ld.global.acquire.gpu.u32 %0, [%1];"
                         : "=r"(v) : "l"(bar) : "memory");
        } while (v < target);
    }
    __syncthreads();
}

__global__ void k_cvt_x(const float4* __restrict__ x) {
    int i = blockIdx.x * 256 + threadIdx.x;
    if (i == 0) { g_bar0 = 0; g_bar1 = 0; g_bari = 0; }
    float4 v = x[i];
    g_x16[i * 2]     = __floats2half2_rn(v.x, v.y);
    g_x16[i * 2 + 1] = __floats2half2_rn(v.z, v.w);
}
__global__ void k_cvt_w(const float4* __restrict__ w) {
    int i = blockIdx.x * 256 + threadIdx.x;
    float4 v = w[i];
    g_w16[i * 2]     = __floats2half2_rn(v.x, v.y);
    g_w16[i * 2 + 1] = __floats2half2_rn(v.z, v.w);
}

// ---- phase A: gi0 = x @ Wih0^T + bih0 ----
__global__ void __launch_bounds__(256) k_gi0(const float* __restrict__ bih0) {
    __shared__ __half2 sA[64 * 32];
    __shared__ __half2 sB[64 * 32];
    const int tid = threadIdx.x, wid = tid >> 5, lane = tid & 31;
    const int wm = wid & 3, wn = wid >> 2, gID = lane >> 2, tg = lane & 3;
    const int m0 = blockIdx.y * 64, n0 = blockIdx.x * 64;
    const uint4* A4 = (const uint4*)g_x16;
    const uint4* B4 = (const uint4*)g_w16;
    const int swz = gID << 2;
    float c[4][4] = {};

    for (int p = 0; p < 8; p++) {
        __syncthreads();
#pragma unroll
        for (int rep = 0; rep < 2; rep++) {
            int idx = rep * 256 + tid, r = idx >> 3, cu = idx & 7;
            int base = (cu * 4) ^ ((r & 7) << 2);
            *(uint4*)&sA[r * 32 + base] = A4[(m0 + r) * 64 + p * 8 + cu];
            *(uint4*)&sB[r * 32 + base] = B4[(n0 + r) * 64 + p * 8 + cu];
        }
        __syncthreads();
#pragma unroll
        for (int ks = 0; ks < 4; ks++) {
            int col = ks * 8 + tg;
            int ra0 = (wm * 16 + gID) * 32, ra1 = ra0 + 8 * 32;
            unsigned a0 = *(const unsigned*)&sA[ra0 + (col ^ swz)];
            unsigned a1 = *(const unsigned*)&sA[ra1 + (col ^ swz)];
            unsigned a2 = *(const unsigned*)&sA[ra0 + ((col + 4) ^ swz)];
            unsigned a3 = *(const unsigned*)&sA[ra1 + ((col + 4) ^ swz)];
#pragma unroll
            for (int nt = 0; nt < 4; nt++) {
                int rb = (wn * 32 + nt * 8 + gID) * 32;
                unsigned b0 = *(const unsigned*)&sB[rb + (col ^ swz)];
                unsigned b1 = *(const unsigned*)&sB[rb + ((col + 4) ^ swz)];
                mma16816(c[nt], a0, a1, a2, a3, b0, b1);
            }
        }
    }
    int mrow = m0 + wm * 16 + gID;
#pragma unroll
    for (int nt = 0; nt < 4; nt++) {
        int nc = n0 + wn * 32 + nt * 8 + tg * 2;
        float b0 = bih0[nc], b1 = bih0[nc + 1];
        int bA = mrow >> 9, tA = mrow & 511;
        g_gi0[((size_t)tA * NB + bA) * 1536 + (nc >> 1)] =
            __floats2half2_rn(c[nt][0] + b0, c[nt][1] + b1);
        int m2 = mrow + 8, bB = m2 >> 9, tB = m2 & 511;
        g_gi0[((size_t)tB * NB + bB) * 1536 + (nc >> 1)] =
            __floats2half2_rn(c[nt][2] + b0, c[nt][3] + b1);
    }
}

// ---- persistent recurrence: fused concurrent GEMMs, 512 threads ----
// smem: sW 36864 h2 | sA1 3x2048 h2 | sA2 3x2048 h2 | sPre [3][64][24]f |
//       sRed [64][24]f | sH0f/sH1f [64][8]f | sBias [72]f
#define SMEM_BYTES ((36864 + 12288) * 4 + (4608 + 1536 + 512 + 512 + 72) * 4)

__global__ void __launch_bounds__(512, 1) k_gru(
    float* __restrict__ out,
    const float* __restrict__ Whh0, const float* __restrict__ Wih1,
    const float* __restrict__ Whh1,
    const float* __restrict__ bhh0, const float* __restrict__ bih1,
    const float* __restrict__ bhh1,
    const float* __restrict__ encH, int hasFinal) {
    extern __shared__ __align__(16) __half2 smem[];
    __half2* sW   = smem;                   // 36864 h2
    __half2* sA1  = smem + 36864;           // 3 x 2048 h2 (64x64 fp16 K-panels)
    __half2* sA2  = sA1 + 6144;             // 3 x 2048 h2
    float*   sPre = (float*)(smem + 36864 + 12288);  // gh0 | gi1 | gh1
    float*   sRed = sPre + 4608;
    float*   sH0f = sRed + 1536;
    float*   sH1f = sH0f + 512;
    float*   sBias = sH1f + 512;

    const int tid = threadIdx.x, wid = tid >> 5, lane = tid & 31;
    const int gID = lane >> 2, tg = lane & 3;
    const int isA = (wid < 8);
    const int mt  = isA ? (wid & 3) : ((wid - 8) & 3);
    const int sel = isA ? (wid >> 2) : ((wid - 8) >> 2);  // A: mat0/1, B: khalf
    const int j0 = blockIdx.x * 8;
    const int b = tid >> 2, jj = (tid & 3) * 2;           // valid for tid<256
    const int swz = gID << 2;
    const int lr = tid >> 3, lcu = tid & 7;               // panel loader
    const int lbase = (lcu * 4) ^ ((lr & 7) << 2);
    const unsigned sA1u = (unsigned)__cvta_generic_to_shared(sA1);
    const unsigned sA2u = (unsigned)__cvta_generic_to_shared(sA2);

    const float* Wm[3] = {Whh0, Wih1, Whh1};
    for (int m = 0; m < 3; m++) {
        const float4* W4 = (const float4*)Wm[m];
        for (int i = tid; i < 24 * 256; i += 512) {
            int r = i >> 8, cu = i & 255;
            int grow = (r >> 3) * NH + j0 + (r & 7);
            float4 v = W4[grow * 256 + cu];
            int base = (cu * 2) ^ ((r & 7) << 2);
            __half2* d = &sW[m * 12288 + r * 512 + base];
            d[0] = __floats2half2_rn(v.x, v.y);
            d[1] = __floats2half2_rn(v.z, v.w);
        }
    }
    const float* Bm[3] = {bhh0, bih1, bhh1};
    if (tid < 72) {
        int m = tid / 24, r = tid % 24;
        sBias[tid] = Bm[m][(r >> 3) * NH + j0 + (r & 7)];
    }
    if (tid < 256) {
        float a = encH[b * NH + j0 + jj], c2 = encH[b * NH + j0 + jj + 1];
        sH0f[b * 8 + jj] = a; sH0f[b * 8 + jj + 1] = c2;
        sH1f[b * 8 + jj] = a; sH1f[b * 8 + jj + 1] = c2;
        __half2 hp = __floats2half2_rn(a, c2);
        g_h0[1][b * 512 + ((j0 + jj) >> 1)] = hp;   // h0^{-1}
        g_h1[0][b * 512 + ((j0 + jj) >> 1)] = hp;   // h1^{-2} dummy
        g_h1[1][b * 512 + ((j0 + jj) >> 1)] = hp;   // h1^{-1}
    }
    bar_arrive(&g_bari);
    bar_wait(&g_bari, GCTA);

    for (int i = 0; i <= NT; i++) {
        __half2 pg0, pg1, pg2;
        if (i < NT) {
            size_t gi = ((size_t)i * NB + b) * 1536 + ((j0 + jj) >> 1);
            pg0 = g_gi0[gi]; pg1 = g_gi0[gi + 512]; pg2 = g_gi0[gi + 1024];
        }
        if (i >= 1) {
            bar_wait(&g_bar0, (unsigned)i * GCTA);   // h0^{i-1} ready
            bar_wait(&g_bar1, (unsigned)i * GCTA);   // h1^{i-2} ready
        }
        const uint4* A1 = (const uint4*)g_h0[(i + 1) & 1];  // h0^{i-1}
        const uint4* A2 = (const uint4*)g_h1[i & 1];        // h1^{i-2}

        float cc[3][4] = {};
        auto issue = [&](int p, int buf) {
            cp16(sA1u + (unsigned)((buf * 2048 + lr * 32 + lbase) * 4),
                 A1 + (size_t)lr * 128 + p * 8 + lcu);
            cp16(sA2u + (unsigned)((buf * 2048 + lr * 32 + lbase) * 4),
                 A2 + (size_t)lr * 128 + p * 8 + lcu);
            cp_commit();
        };
        issue(0, 0); issue(1, 1);

        for (int p = 0; p < 16; p++) {
            if (p < 15) cp_wait<1>(); else cp_wait<0>();
            __syncthreads();
            if (p + 2 < 16) issue(p + 2, (p + 2) % 3);
            const int ra0 = (mt * 16 + gID) * 32, ra1 = ra0 + 256;
            if (isA) {
                const __half2* sAb = sA1 + (p % 3) * 2048;
                const __half2* bw = &sW[sel * 12288 + gID * 512];
#pragma unroll
                for (int ks = 0; ks < 4; ks++) {
                    int col = ks * 8 + tg;
                    unsigned a0 = *(const unsigned*)&sAb[ra0 + (col ^ swz)];
                    unsigned a1 = *(const unsigned*)&sAb[ra1 + (col ^ swz)];
                    unsigned a2 = *(const unsigned*)&sAb[ra0 + ((col + 4) ^ swz)];
                    unsigned a3 = *(const unsigned*)&sAb[ra1 + ((col + 4) ^ swz)];
                    int gk8 = (p * 4 + ks) * 8 + tg;
#pragma unroll
                    for (int g = 0; g < 3; g++) {
                        unsigned b0 = *(const unsigned*)&bw[g * 4096 + (gk8 ^ swz)];
                        unsigned b1 = *(const unsigned*)&bw[g * 4096 + ((gk8 + 4) ^ swz)];
                        mma16816(cc[g], a0, a1, a2, a3, b0, b1);
                    }
                }
            } else {
                const __half2* sAb = sA2 + (p % 3) * 2048;
                const __half2* bw = &sW[2 * 12288 + gID * 512];
#pragma unroll
                for (int ks2 = 0; ks2 < 2; ks2++) {
                    int ks = sel * 2 + ks2;
                    int col = ks * 8 + tg;
                    unsigned a0 = *(const unsigned*)&sAb[ra0 + (col ^ swz)];
                    unsigned a1 = *(const unsigned*)&sAb[ra1 + (col ^ swz)];
                    unsigned a2 = *(const unsigned*)&sAb[ra0 + ((col + 4) ^ swz)];
                    unsigned a3 = *(const unsigned*)&sAb[ra1 + ((col + 4) ^ swz)];
                    int gk8 = (p * 4 + ks) * 8 + tg;
#pragma unroll
                    for (int g = 0; g < 3; g++) {
                        unsigned b0 = *(const unsigned*)&bw[g * 4096 + (gk8 ^ swz)];
                        unsigned b1 = *(const unsigned*)&bw[g * 4096 + ((gk8 + 4) ^ swz)];
                        mma16816(cc[g], a0, a1, a2, a3, b0, b1);
                    }
                }
            }
        }
        __syncthreads();

        // epilogue: gh0 -> sPre[0], gi1 -> sPre[1536], gh1 -> sPre[3072]
        int m0r = mt * 16 + gID, nc = 2 * tg;
        if (isA) {
            float* dst = sPre + sel * 1536;
#pragma unroll
            for (int g = 0; g < 3; g++) {
                *(float2*)&dst[m0r * 24 + g * 8 + nc]       = make_float2(cc[g][0], cc[g][1]);
                *(float2*)&dst[(m0r + 8) * 24 + g * 8 + nc] = make_float2(cc[g][2], cc[g][3]);
            }
        } else if (sel == 1) {
#pragma unroll
            for (int g = 0; g < 3; g++) {
                *(float2*)&sRed[m0r * 24 + g * 8 + nc]       = make_float2(cc[g][0], cc[g][1]);
                *(float2*)&sRed[(m0r + 8) * 24 + g * 8 + nc] = make_float2(cc[g][2], cc[g][3]);
            }
        }
        __syncthreads();
        if (!isA && sel == 0) {
#pragma unroll
            for (int g = 0; g < 3; g++) {
                float2 r0 = *(float2*)&sRed[m0r * 24 + g * 8 + nc];
                float2 r1 = *(float2*)&sRed[(m0r + 8) * 24 + g * 8 + nc];
                *(float2*)&sPre[3072 + m0r * 24 + g * 8 + nc]       = make_float2(cc[g][0] + r0.x, cc[g][1] + r0.y);
                *(float2*)&sPre[3072 + (m0r + 8) * 24 + g * 8 + nc] = make_float2(cc[g][2] + r1.x, cc[g][3] + r1.y);
            }
        }
        __syncthreads();

        // L0 elementwise step i, publish h0^i
        if (i < NT) {
            if (tid < 256) {
                float gir[2] = {__low2float(pg0), __high2float(pg0)};
                float giz[2] = {__low2float(pg1), __high2float(pg1)};
                float gin[2] = {__low2float(pg2), __high2float(pg2)};
                float h0n[2];
#pragma unroll
                for (int d = 0; d < 2; d++) {
                    int j = jj + d;
                    float r = sigm(gir[d] + sPre[b * 24 + j]      + sBias[j]);
                    float z = sigm(giz[d] + sPre[b * 24 + 8 + j]  + sBias[8 + j]);
                    float n = tanhf(gin[d] + r * (sPre[b * 24 + 16 + j] + sBias[16 + j]));
                    h0n[d] = (1.0f - z) * n + z * sH0f[b * 8 + j];
                }
                sH0f[b * 8 + jj] = h0n[0]; sH0f[b * 8 + jj + 1] = h0n[1];
                g_h0[i & 1][b * 512 + ((j0 + jj) >> 1)] = __floats2half2_rn(h0n[0], h0n[1]);
            }
            bar_arrive(&g_bar0);
        }

        // L1 elementwise step i-1, publish h1^{i-1} + output
        if (i >= 1) {
            if (tid < 256) {
                int t = i - 1;
                float h1n[2];
#pragma unroll
                for (int d = 0; d < 2; d++) {
                    int j = jj + d;
                    float r = sigm(sPre[1536 + b * 24 + j]     + sBias[24 + j] +
                                   sPre[3072 + b * 24 + j]     + sBias[48 + j]);
                    float z = sigm(sPre[1536 + b * 24 + 8 + j] + sBias[32 + j] +
                                   sPre[3072 + b * 24 + 8 + j] + sBias[56 + j]);
                    float n = tanhf(sPre[1536 + b * 24 + 16 + j] + sBias[40 + j] +
                                    r * (sPre[3072 + b * 24 + 16 + j] + sBias[64 + j]));
                    h1n[d] = (1.0f - z) * n + z * sH1f[b * 8 + j];
                }
                sH1f[b * 8 + jj] = h1n[0]; sH1f[b * 8 + jj + 1] = h1n[1];
                g_h1[(i + 1) & 1][b * 512 + ((j0 + jj) >> 1)] = __floats2half2_rn(h1n[0], h1n[1]);
                *(float2*)&out[((size_t)b * NT + t) * NH + j0 + jj] = make_float2(h1n[0], h1n[1]);
                if (hasFinal && t == NT - 1) {
                    float* o2 = out + (size_t)NB * NT * NH;
                    *(float2*)&o2[b * NH + j0 + jj] = make_float2(h1n[0], h1n[1]);
                }
            }
        }
        if (i < NT) bar_arrive(&g_bar1);
    }
}

extern "C" void kernel_launch(void* const* d_in, const int* in_sizes, int n_in,
                              void* d_out, int out_size) {
    const float* x    = (const float*)d_in[0];
    const float* encH = (const float*)d_in[2];
    const float* Wih0 = (const float*)d_in[3];
    const float* Whh0 = (const float*)d_in[4];
    const float* bih0 = (const float*)d_in[5];
    const float* bhh0 = (const float*)d_in[6];
    const float* Wih1 = (const float*)d_in[7];
    const float* Whh1 = (const float*)d_in[8];
    const float* bih1 = (const float*)d_in[9];
    const float* bhh1 = (const float*)d_in[10];
    float* out = (float*)d_out;
    int hasFinal = (out_size >= NB * NT * NH + NB * NH) ? 1 : 0;

    cudaFuncSetAttribute(k_gru, cudaFuncAttributeMaxDynamicSharedMemorySize, SMEM_BYTES);

    k_cvt_x<<<16384, 256>>>((const float4*)x);
    k_cvt_w<<<1536, 256>>>((const float4*)Wih0);
    dim3 g1(48, 512);
    k_gi0<<<g1, 256>>>(bih0);
    k_gru<<<GCTA, 512, SMEM_BYTES>>>(out, Whh0, Wih1, Whh1,
                                     bhh0, bih1, bhh1, encH, hasFinal);
}

// round 8
// speedup vs baseline: 1.8534x; 1.8534x over previous
#include <cuda_runtime.h>
#include <cuda_fp16.h>
#include <math.h>

#define NB   64
#define NT   512
#define NIN  512
#define NH   1024
#define NH3  3072
#define GCTA 128

__device__ __half2  g_x16[NB * NT * NIN / 2];
__device__ __half2  g_w16[NH3 * NIN / 2];
__device__ __half2  g_gi0[(size_t)NB * NT * NH3 / 2];  // [t][b][3072] fp16, +bias
__device__ __half2  g_h0[2][NB * NH / 2];
__device__ __half2  g_h1[2][NB * NH / 2];
__device__ unsigned g_bar0, g_bar1, g_bari;

__device__ __forceinline__ float sigm(float x) { return 1.0f / (1.0f + __expf(-x)); }

__device__ __forceinline__ void mma16816(float* c, unsigned a0, unsigned a1,
                                         unsigned a2, unsigned a3,
                                         unsigned b0, unsigned b1) {
    asm volatile(
        "mma.sync.aligned.m16n8k16.row.col.f32.f16.f16.f32 "
        "{%0,%1,%2,%3},{%4,%5,%6,%7},{%8,%9},{%0,%1,%2,%3};\n"
        : "+f"(c[0]), "+f"(c[1]), "+f"(c[2]), "+f"(c[3])
        : "r"(a0), "r"(a1), "r"(a2), "r"(a3), "r"(b0), "r"(b1));
}

__device__ __forceinline__ void ldsm4(unsigned& r0, unsigned& r1,
                                      unsigned& r2, unsigned& r3,
                                      const __half2* p) {
    unsigned a = (unsigned)__cvta_generic_to_shared(p);
    asm volatile("ldmatrix.sync.aligned.m8n8.x4.shared.b16 {%0,%1,%2,%3}, [%4];"
                 : "=r"(r0), "=r"(r1), "=r"(r2), "=r"(r3) : "r"(a));
}

__device__ __forceinline__ void cp16(unsigned dst, const void* src) {
    asm volatile("cp.async.cg.shared.global [%0], [%1], 16;" :: "r"(dst), "l"(src));
}
__device__ __forceinline__ void cp_commit() { asm volatile("cp.async.commit_group;"); }
template <int N> __device__ __forceinline__ void cp_wait() {
    asm volatile("cp.async.wait_group %0;" :: "n"(N));
}

__device__ __forceinline__ void bar_arrive(unsigned* bar) {
    __syncthreads();
    if (threadIdx.x == 0) { __threadfence(); atomicAdd(bar, 1u); }
}
__device__ __forceinline__ void bar_wait(unsigned* bar, unsigned target) {
    if (threadIdx.x == 0) {
        unsigned v;
        do {
            asm volatile("ld.global.acquire.gpu.u32 %0, [%1];"
                         : "=r"(v) : "l"(bar) : "memory");
        } while (v < target);
    }
    __syncthreads();
}

__global__ void k_cvt_x(const float4* __restrict__ x) {
    int i = blockIdx.x * 256 + threadIdx.x;
    if (i == 0) { g_bar0 = 0; g_bar1 = 0; g_bari = 0; }
    float4 v = x[i];
    g_x16[i * 2]     = __floats2half2_rn(v.x, v.y);
    g_x16[i * 2 + 1] = __floats2half2_rn(v.z, v.w);
}
__global__ void k_cvt_w(const float4* __restrict__ w) {
    int i = blockIdx.x * 256 + threadIdx.x;
    float4 v = w[i];
    g_w16[i * 2]     = __floats2half2_rn(v.x, v.y);
    g_w16[i * 2 + 1] = __floats2half2_rn(v.z, v.w);
}

// ---- phase A: gi0 = x @ Wih0^T + bih0 ----
__global__ void __launch_bounds__(256) k_gi0(const float* __restrict__ bih0) {
    __shared__ __half2 sA[64 * 32];
    __shared__ __half2 sB[64 * 32];
    const int tid = threadIdx.x, wid = tid >> 5, lane = tid & 31;
    const int wm = wid & 3, wn = wid >> 2, gID = lane >> 2, tg = lane & 3;
    const int m0 = blockIdx.y * 64, n0 = blockIdx.x * 64;
    const uint4* A4 = (const uint4*)g_x16;
    const uint4* B4 = (const uint4*)g_w16;
    const int swz = gID << 2;
    float c[4][4] = {};

    for (int p = 0; p < 8; p++) {
        __syncthreads();
#pragma unroll
        for (int rep = 0; rep < 2; rep++) {
            int idx = rep * 256 + tid, r = idx >> 3, cu = idx & 7;
            int base = (cu * 4) ^ ((r & 7) << 2);
            *(uint4*)&sA[r * 32 + base] = A4[(m0 + r) * 64 + p * 8 + cu];
            *(uint4*)&sB[r * 32 + base] = B4[(n0 + r) * 64 + p * 8 + cu];
        }
        __syncthreads();
#pragma unroll
        for (int ks = 0; ks < 4; ks++) {
            int col = ks * 8 + tg;
            int ra0 = (wm * 16 + gID) * 32, ra1 = ra0 + 8 * 32;
            unsigned a0 = *(const unsigned*)&sA[ra0 + (col ^ swz)];
            unsigned a1 = *(const unsigned*)&sA[ra1 + (col ^ swz)];
            unsigned a2 = *(const unsigned*)&sA[ra0 + ((col + 4) ^ swz)];
            unsigned a3 = *(const unsigned*)&sA[ra1 + ((col + 4) ^ swz)];
#pragma unroll
            for (int nt = 0; nt < 4; nt++) {
                int rb = (wn * 32 + nt * 8 + gID) * 32;
                unsigned b0 = *(const unsigned*)&sB[rb + (col ^ swz)];
                unsigned b1 = *(const unsigned*)&sB[rb + ((col + 4) ^ swz)];
                mma16816(c[nt], a0, a1, a2, a3, b0, b1);
            }
        }
    }
    int mrow = m0 + wm * 16 + gID;
#pragma unroll
    for (int nt = 0; nt < 4; nt++) {
        int nc = n0 + wn * 32 + nt * 8 + tg * 2;
        float b0 = bih0[nc], b1 = bih0[nc + 1];
        int bA = mrow >> 9, tA = mrow & 511;
        g_gi0[((size_t)tA * NB + bA) * 1536 + (nc >> 1)] =
            __floats2half2_rn(c[nt][0] + b0, c[nt][1] + b1);
        int m2 = mrow + 8, bB = m2 >> 9, tB = m2 & 511;
        g_gi0[((size_t)tB * NB + bB) * 1536 + (nc >> 1)] =
            __floats2half2_rn(c[nt][2] + b0, c[nt][3] + b1);
    }
}

// ---- persistent recurrence (R5 structure + ldmatrix fragment feeds) ----
#define SMEM_BYTES ((36864 + 12288) * 4 + (4608 + 1536 + 512 + 512 + 72) * 4)

__global__ void __launch_bounds__(256, 1) k_gru(
    float* __restrict__ out,
    const float* __restrict__ Whh0, const float* __restrict__ Wih1,
    const float* __restrict__ Whh1,
    const float* __restrict__ bhh0, const float* __restrict__ bih1,
    const float* __restrict__ bhh1,
    const float* __restrict__ encH, int hasFinal) {
    extern __shared__ __align__(16) __half2 smem[];
    __half2* sW   = smem;                  // 36864 h2
    __half2* sA   = smem + 36864;          // 3 x 4096 h2 (64x128 fp16 panels)
    float*   sPre = (float*)(smem + 36864 + 12288);  // gh0 | gi1(persists) | gh1
    float*   sRed = sPre + 4608;
    float*   sH0f = sRed + 1536;
    float*   sH1f = sH0f + 512;
    float*   sBias = sH1f + 512;

    const int tid = threadIdx.x, wid = tid >> 5, lane = tid & 31;
    const int mt = wid & 3, ng = wid >> 2, gID = lane >> 2, tg = lane & 3;
    const int j0 = blockIdx.x * 8;
    const int b = tid >> 2, jj = (tid & 3) * 2;
    const int lr = tid >> 4, lc = tid & 15;
    const int lbase = (lc * 4) ^ ((lr & 7) << 2);
    const unsigned sAu = (unsigned)__cvta_generic_to_shared(sA);

    // LDSM per-lane addressing
    const int arow = mt * 16 + (lane & 15);          // A fragment row
    const int aoff = arow * 64;
    const int asw  = (arow & 7) << 2;
    const int alo  = (lane >> 4);                    // 0..1: k-half of chunk pair
    const int brow = lane & 7;                       // B row within gate block
    const int bsw  = brow << 2;
    const int blo  = (lane >> 3);                    // 0..3: chunk within 2 k-steps

    const float* Wm[3] = {Whh0, Wih1, Whh1};
    for (int m = 0; m < 3; m++) {
        const float4* W4 = (const float4*)Wm[m];
        for (int i = tid; i < 24 * 256; i += 256) {
            int r = i >> 8, cu = i & 255;
            int grow = (r >> 3) * NH + j0 + (r & 7);
            float4 v = W4[grow * 256 + cu];
            int base = (cu * 2) ^ ((r & 7) << 2);
            __half2* d = &sW[m * 12288 + r * 512 + base];
            d[0] = __floats2half2_rn(v.x, v.y);
            d[1] = __floats2half2_rn(v.z, v.w);
        }
    }
    const float* Bm[3] = {bhh0, bih1, bhh1};
    if (tid < 72) {
        int m = tid / 24, r = tid % 24;
        sBias[tid] = Bm[m][(r >> 3) * NH + j0 + (r & 7)];
    }
    {
        float a = encH[b * NH + j0 + jj], c2 = encH[b * NH + j0 + jj + 1];
        sH0f[b * 8 + jj] = a; sH0f[b * 8 + jj + 1] = c2;
        sH1f[b * 8 + jj] = a; sH1f[b * 8 + jj + 1] = c2;
        __half2 hp = __floats2half2_rn(a, c2);
        g_h0[1][b * 512 + ((j0 + jj) >> 1)] = hp;   // h0^{-1}
        g_h1[1][b * 512 + ((j0 + jj) >> 1)] = hp;   // h1^{-1}
    }
    bar_arrive(&g_bari);
    bar_wait(&g_bari, GCTA);

    auto issue_panel = [&](const uint4* A4, int p, int buf) {
#pragma unroll
        for (int q = 0; q < 4; q++)
            cp16(sAu + (unsigned)((buf * 4096 + (lr + q * 16) * 64 + lbase) * 4),
                 A4 + (size_t)(lr + q * 16) * 128 + p * 16 + lc);
        cp_commit();
    };

    for (int i = 0; i <= NT + 1; i++) {
        __half2 pg0, pg1, pg2;
        if (i < NT) {
            size_t gi = ((size_t)i * NB + b) * 1536 + ((j0 + jj) >> 1);
            pg0 = g_gi0[gi]; pg1 = g_gi0[gi + 512]; pg2 = g_gi0[gi + 1024];
        }

        // ---- phase 1: wait bar1 (h1^{i-3} visible) ----
        if (i >= 3) bar_wait(&g_bar1, (unsigned)(i - 2) * GCTA);

        // ---- phase 2: gh1 = Whh1 @ h1^{i-3} ----
        if (i >= 2) {
            const uint4* A2 = (const uint4*)g_h1[(i + 1) & 1];
            float cB[3][4] = {};
            issue_panel(A2, 0, 0);
            issue_panel(A2, 1, 1);
            for (int p = 0; p < 8; p++) {
                if (p < 7) cp_wait<1>(); else cp_wait<0>();
                __syncthreads();
                if (p + 2 < 8) issue_panel(A2, p + 2, (p + 2) % 3);
                const __half2* aB = sA + (p % 3) * 4096 + aoff;
                const __half2* wb = sW + 2 * 12288 + brow * 512;
#pragma unroll
                for (int pr = 0; pr < 2; pr++) {
                    int s0 = ng * 4 + pr * 2;
                    unsigned a0, a1, a2, a3, e0, e1, e2, e3;
                    int ca = (2 * s0 + alo) * 4;
                    ldsm4(a0, a1, a2, a3, aB + (ca ^ asw));
                    ldsm4(e0, e1, e2, e3, aB + ((ca + 8) ^ asw));
                    int cb = (2 * (p * 8 + s0) + blo) * 4;
                    unsigned b0[4], b1[4], b2[4];
                    ldsm4(b0[0], b0[1], b0[2], b0[3], wb + (cb ^ bsw));
                    ldsm4(b1[0], b1[1], b1[2], b1[3], wb + 4096 + (cb ^ bsw));
                    ldsm4(b2[0], b2[1], b2[2], b2[3], wb + 8192 + (cb ^ bsw));
                    mma16816(cB[0], a0, a1, a2, a3, b0[0], b0[1]);
                    mma16816(cB[1], a0, a1, a2, a3, b1[0], b1[1]);
                    mma16816(cB[2], a0, a1, a2, a3, b2[0], b2[1]);
                    mma16816(cB[0], e0, e1, e2, e3, b0[2], b0[3]);
                    mma16816(cB[1], e0, e1, e2, e3, b1[2], b1[3]);
                    mma16816(cB[2], e0, e1, e2, e3, b2[2], b2[3]);
                }
            }
            __syncthreads();
            int m0r = mt * 16 + gID, nc = 2 * tg;
            if (ng == 1) {
#pragma unroll
                for (int g = 0; g < 3; g++) {
                    *(float2*)&sRed[m0r * 24 + g * 8 + nc]       = make_float2(cB[g][0], cB[g][1]);
                    *(float2*)&sRed[(m0r + 8) * 24 + g * 8 + nc] = make_float2(cB[g][2], cB[g][3]);
                }
            }
            __syncthreads();
            if (ng == 0) {
#pragma unroll
                for (int g = 0; g < 3; g++) {
                    float2 r0 = *(float2*)&sRed[m0r * 24 + g * 8 + nc];
                    float2 r1 = *(float2*)&sRed[(m0r + 8) * 24 + g * 8 + nc];
                    *(float2*)&sPre[3072 + m0r * 24 + g * 8 + nc]       = make_float2(cB[g][0] + r0.x, cB[g][1] + r0.y);
                    *(float2*)&sPre[3072 + (m0r + 8) * 24 + g * 8 + nc] = make_float2(cB[g][2] + r1.x, cB[g][3] + r1.y);
                }
            }
            __syncthreads();

            // ---- phase 3: L1 elementwise step t=i-2 ----
            int t = i - 2;
            float h1n[2];
#pragma unroll
            for (int d = 0; d < 2; d++) {
                int j = jj + d;
                float r = sigm(sPre[1536 + b * 24 + j]     + sBias[24 + j] +
                               sPre[3072 + b * 24 + j]     + sBias[48 + j]);
                float z = sigm(sPre[1536 + b * 24 + 8 + j] + sBias[32 + j] +
                               sPre[3072 + b * 24 + 8 + j] + sBias[56 + j]);
                float n = tanhf(sPre[1536 + b * 24 + 16 + j] + sBias[40 + j] +
                                r * (sPre[3072 + b * 24 + 16 + j] + sBias[64 + j]));
                h1n[d] = (1.0f - z) * n + z * sH1f[b * 8 + j];
            }
            sH1f[b * 8 + jj] = h1n[0]; sH1f[b * 8 + jj + 1] = h1n[1];
            g_h1[i & 1][b * 512 + ((j0 + jj) >> 1)] = __floats2half2_rn(h1n[0], h1n[1]);
            *(float2*)&out[((size_t)b * NT + t) * NH + j0 + jj] = make_float2(h1n[0], h1n[1]);
            if (hasFinal && t == NT - 1) {
                float* o2 = out + (size_t)NB * NT * NH;
                *(float2*)&o2[b * NH + j0 + jj] = make_float2(h1n[0], h1n[1]);
            }
            if (i <= NT) bar_arrive(&g_bar1);
            else __syncthreads();
        }

        if (i > NT) break;

        // ---- phase 4: wait bar0, (Whh0|Wih1) @ h0^{i-1} ----
        if (i >= 1) bar_wait(&g_bar0, (unsigned)i * GCTA);
        {
            const uint4* A1 = (const uint4*)g_h0[(i + 1) & 1];
            float cA[3][4] = {};
            issue_panel(A1, 0, 0);
            issue_panel(A1, 1, 1);
            for (int p = 0; p < 8; p++) {
                if (p < 7) cp_wait<1>(); else cp_wait<0>();
                __syncthreads();
                if (p + 2 < 8) issue_panel(A1, p + 2, (p + 2) % 3);
                const __half2* aB = sA + (p % 3) * 4096 + aoff;
                const __half2* wb = sW + ng * 12288 + brow * 512;
#pragma unroll
                for (int pr = 0; pr < 4; pr++) {
                    int s0 = pr * 2;
                    unsigned a0, a1, a2, a3, e0, e1, e2, e3;
                    int ca = (2 * s0 + alo) * 4;
                    ldsm4(a0, a1, a2, a3, aB + (ca ^ asw));
                    ldsm4(e0, e1, e2, e3, aB + ((ca + 8) ^ asw));
                    int cb = (2 * (p * 8 + s0) + blo) * 4;
                    unsigned b0[4], b1[4], b2[4];
                    ldsm4(b0[0], b0[1], b0[2], b0[3], wb + (cb ^ bsw));
                    ldsm4(b1[0], b1[1], b1[2], b1[3], wb + 4096 + (cb ^ bsw));
                    ldsm4(b2[0], b2[1], b2[2], b2[3], wb + 8192 + (cb ^ bsw));
                    mma16816(cA[0], a0, a1, a2, a3, b0[0], b0[1]);
                    mma16816(cA[1], a0, a1, a2, a3, b1[0], b1[1]);
                    mma16816(cA[2], a0, a1, a2, a3, b2[0], b2[1]);
                    mma16816(cA[0], e0, e1, e2, e3, b0[2], b0[3]);
                    mma16816(cA[1], e0, e1, e2, e3, b1[2], b1[3]);
                    mma16816(cA[2], e0, e1, e2, e3, b2[2], b2[3]);
                }
            }
            __syncthreads();
            int m0r = mt * 16 + gID, nc = 2 * tg;
            float* dst = (ng == 0) ? sPre : sPre + 1536;
#pragma unroll
            for (int g = 0; g < 3; g++) {
                *(float2*)&dst[m0r * 24 + g * 8 + nc]       = make_float2(cA[g][0], cA[g][1]);
                *(float2*)&dst[(m0r + 8) * 24 + g * 8 + nc] = make_float2(cA[g][2], cA[g][3]);
            }
            __syncthreads();
        }

        // ---- phase 5: L0 elementwise step i ----
        if (i < NT) {
            float gir[2] = {__low2float(pg0), __high2float(pg0)};
            float giz[2] = {__low2float(pg1), __high2float(pg1)};
            float gin[2] = {__low2float(pg2), __high2float(pg2)};
            float h0n[2];
#pragma unroll
            for (int d = 0; d < 2; d++) {
                int j = jj + d;
                float r = sigm(gir[d] + sPre[b * 24 + j]      + sBias[j]);
                float z = sigm(giz[d] + sPre[b * 24 + 8 + j]  + sBias[8 + j]);
                float n = tanhf(gin[d] + r * (sPre[b * 24 + 16 + j] + sBias[16 + j]));
                h0n[d] = (1.0f - z) * n + z * sH0f[b * 8 + j];
            }
            sH0f[b * 8 + jj] = h0n[0]; sH0f[b * 8 + jj + 1] = h0n[1];
            g_h0[i & 1][b * 512 + ((j0 + jj) >> 1)] = __floats2half2_rn(h0n[0], h0n[1]);
            bar_arrive(&g_bar0);
        }
    }
}

extern "C" void kernel_launch(void* const* d_in, const int* in_sizes, int n_in,
                              void* d_out, int out_size) {
    const float* x    = (const float*)d_in[0];
    const float* encH = (const float*)d_in[2];
    const float* Wih0 = (const float*)d_in[3];
    const float* Whh0 = (const float*)d_in[4];
    const float* bih0 = (const float*)d_in[5];
    const float* bhh0 = (const float*)d_in[6];
    const float* Wih1 = (const float*)d_in[7];
    const float* Whh1 = (const float*)d_in[8];
    const float* bih1 = (const float*)d_in[9];
    const float* bhh1 = (const float*)d_in[10];
    float* out = (float*)d_out;
    int hasFinal = (out_size >= NB * NT * NH + NB * NH) ? 1 : 0;

    cudaFuncSetAttribute(k_gru, cudaFuncAttributeMaxDynamicSharedMemorySize, SMEM_BYTES);

    k_cvt_x<<<16384, 256>>>((const float4*)x);
    k_cvt_w<<<1536, 256>>>((const float4*)Wih0);
    dim3 g1(48, 512);
    k_gi0<<<g1, 256>>>(bih0);
    k_gru<<<GCTA, 256, SMEM_BYTES>>>(out, Whh0, Wih1, Whh1,
                                     bhh0, bih1, bhh1, encH, hasFinal);
}

// round 9
// speedup vs baseline: 2.0764x; 1.1203x over previous
#include <cuda_runtime.h>
#include <cuda_fp16.h>
#include <math.h>

#define NB   64
#define NT   512
#define NIN  512
#define NH   1024
#define NH3  3072
#define GCTA 128

__device__ __half2  g_x16[NB * NT * NIN / 2];
__device__ __half2  g_w16[NH3 * NIN / 2];
__device__ __half2  g_gi0[(size_t)NB * NT * NH3 / 2];  // [t][b][3072] fp16, +bias
__device__ __half2  g_h0[2][NB * NH / 2];
__device__ __half2  g_h1[2][NB * NH / 2];
__device__ unsigned g_bar0, g_bar1, g_bari;

__device__ __forceinline__ float sigm(float x) { return 1.0f / (1.0f + __expf(-x)); }

__device__ __forceinline__ void mma16816(float* c, unsigned a0, unsigned a1,
                                         unsigned a2, unsigned a3,
                                         unsigned b0, unsigned b1) {
    asm volatile(
        "mma.sync.aligned.m16n8k16.row.col.f32.f16.f16.f32 "
        "{%0,%1,%2,%3},{%4,%5,%6,%7},{%8,%9},{%0,%1,%2,%3};\n"
        : "+f"(c[0]), "+f"(c[1]), "+f"(c[2]), "+f"(c[3])
        : "r"(a0), "r"(a1), "r"(a2), "r"(a3), "r"(b0), "r"(b1));
}

__device__ __forceinline__ void ldsm4(unsigned& r0, unsigned& r1,
                                      unsigned& r2, unsigned& r3,
                                      const __half2* p) {
    unsigned a = (unsigned)__cvta_generic_to_shared(p);
    asm volatile("ldmatrix.sync.aligned.m8n8.x4.shared.b16 {%0,%1,%2,%3}, [%4];"
                 : "=r"(r0), "=r"(r1), "=r"(r2), "=r"(r3) : "r"(a));
}

__device__ __forceinline__ void cp16(unsigned dst, const void* src) {
    asm volatile("cp.async.cg.shared.global [%0], [%1], 16;" :: "r"(dst), "l"(src));
}
__device__ __forceinline__ void cp_commit() { asm volatile("cp.async.commit_group;"); }
template <int N> __device__ __forceinline__ void cp_wait() {
    asm volatile("cp.async.wait_group %0;" :: "n"(N));
}

__device__ __forceinline__ void bar_arrive(unsigned* bar) {
    __syncthreads();
    if (threadIdx.x == 0) { __threadfence(); atomicAdd(bar, 1u); }
}
__device__ __forceinline__ void bar_wait(unsigned* bar, unsigned target) {
    if (threadIdx.x == 0) {
        unsigned v;
        do {
            asm volatile("ld.global.acquire.gpu.u32 %0, [%1];"
                         : "=r"(v) : "l"(bar) : "memory");
        } while (v < target);
    }
    __syncthreads();
}

__global__ void k_cvt_x(const float4* __restrict__ x) {
    int i = blockIdx.x * 256 + threadIdx.x;
    if (i == 0) { g_bar0 = 0; g_bar1 = 0; g_bari = 0; }
    float4 v = x[i];
    g_x16[i * 2]     = __floats2half2_rn(v.x, v.y);
    g_x16[i * 2 + 1] = __floats2half2_rn(v.z, v.w);
}
__global__ void k_cvt_w(const float4* __restrict__ w) {
    int i = blockIdx.x * 256 + threadIdx.x;
    float4 v = w[i];
    g_w16[i * 2]     = __floats2half2_rn(v.x, v.y);
    g_w16[i * 2 + 1] = __floats2half2_rn(v.z, v.w);
}

// ---- phase A: gi0 = x @ Wih0^T + bih0 ----
__global__ void __launch_bounds__(256) k_gi0(const float* __restrict__ bih0) {
    __shared__ __half2 sA[64 * 32];
    __shared__ __half2 sB[64 * 32];
    const int tid = threadIdx.x, wid = tid >> 5, lane = tid & 31;
    const int wm = wid & 3, wn = wid >> 2, gID = lane >> 2, tg = lane & 3;
    const int m0 = blockIdx.y * 64, n0 = blockIdx.x * 64;
    const uint4* A4 = (const uint4*)g_x16;
    const uint4* B4 = (const uint4*)g_w16;
    const int swz = gID << 2;
    float c[4][4] = {};

    for (int p = 0; p < 8; p++) {
        __syncthreads();
#pragma unroll
        for (int rep = 0; rep < 2; rep++) {
            int idx = rep * 256 + tid, r = idx >> 3, cu = idx & 7;
            int base = (cu * 4) ^ ((r & 7) << 2);
            *(uint4*)&sA[r * 32 + base] = A4[(m0 + r) * 64 + p * 8 + cu];
            *(uint4*)&sB[r * 32 + base] = B4[(n0 + r) * 64 + p * 8 + cu];
        }
        __syncthreads();
#pragma unroll
        for (int ks = 0; ks < 4; ks++) {
            int col = ks * 8 + tg;
            int ra0 = (wm * 16 + gID) * 32, ra1 = ra0 + 8 * 32;
            unsigned a0 = *(const unsigned*)&sA[ra0 + (col ^ swz)];
            unsigned a1 = *(const unsigned*)&sA[ra1 + (col ^ swz)];
            unsigned a2 = *(const unsigned*)&sA[ra0 + ((col + 4) ^ swz)];
            unsigned a3 = *(const unsigned*)&sA[ra1 + ((col + 4) ^ swz)];
#pragma unroll
            for (int nt = 0; nt < 4; nt++) {
                int rb = (wn * 32 + nt * 8 + gID) * 32;
                unsigned b0 = *(const unsigned*)&sB[rb + (col ^ swz)];
                unsigned b1 = *(const unsigned*)&sB[rb + ((col + 4) ^ swz)];
                mma16816(c[nt], a0, a1, a2, a3, b0, b1);
            }
        }
    }
    int mrow = m0 + wm * 16 + gID;
#pragma unroll
    for (int nt = 0; nt < 4; nt++) {
        int nc = n0 + wn * 32 + nt * 8 + tg * 2;
        float b0 = bih0[nc], b1 = bih0[nc + 1];
        int bA = mrow >> 9, tA = mrow & 511;
        g_gi0[((size_t)tA * NB + bA) * 1536 + (nc >> 1)] =
            __floats2half2_rn(c[nt][0] + b0, c[nt][1] + b1);
        int m2 = mrow + 8, bB = m2 >> 9, tB = m2 & 511;
        g_gi0[((size_t)tB * NB + bB) * 1536 + (nc >> 1)] =
            __floats2half2_rn(c[nt][2] + b0, c[nt][3] + b1);
    }
}

// ---- persistent recurrence: 12 uniform warps, one merged GEMM pipeline ----
// smem: sW 36864 h2 | sA1 3x2048 h2 | sA2 3x2048 h2 | sPre [3][64][24]f |
//       sH0f/sH1f [64][8]f | sBias [72]f
#define SMEM_BYTES ((36864 + 12288) * 4 + (4608 + 512 + 512 + 72) * 4)

__global__ void __launch_bounds__(384, 1) k_gru(
    float* __restrict__ out,
    const float* __restrict__ Whh0, const float* __restrict__ Wih1,
    const float* __restrict__ Whh1,
    const float* __restrict__ bhh0, const float* __restrict__ bih1,
    const float* __restrict__ bhh1,
    const float* __restrict__ encH, int hasFinal) {
    extern __shared__ __align__(16) __half2 smem[];
    __half2* sW   = smem;                  // 36864 h2
    __half2* sA1  = smem + 36864;          // 3 x 2048 h2 (64x64 fp16 panels)
    __half2* sA2  = sA1 + 6144;            // 3 x 2048 h2
    float*   sPre = (float*)(smem + 36864 + 12288);  // gh0 | gi1 | gh1
    float*   sH0f = sPre + 4608;
    float*   sH1f = sH0f + 512;
    float*   sBias = sH1f + 512;

    const int tid = threadIdx.x, wid = tid >> 5, lane = tid & 31;
    const int msel = wid >> 2;              // 0,1,2 : Whh0 / Wih1 / Whh1
    const int mt   = wid & 1;               // m-half (rows mt*32..mt*32+31)
    const int kh   = (wid >> 1) & 1;        // k-half within each panel
    const int gID = lane >> 2, tg = lane & 3;
    const int j0 = blockIdx.x * 8;
    const int b = tid >> 2, jj = (tid & 3) * 2;   // valid tid<256
    // LDSM addressing
    const int l15 = lane & 15, alo = lane >> 4;
    const int asw = (lane & 7) << 2;
    const int aoff0 = (mt * 32 + l15) * 32;
    const int aoff1 = aoff0 + 16 * 32;
    const int brow = lane & 7, bsw = brow << 2, blo = lane >> 3;
    const unsigned sA1u = (unsigned)__cvta_generic_to_shared(sA1);
    const unsigned sA2u = (unsigned)__cvta_generic_to_shared(sA2);

    const float* Wm[3] = {Whh0, Wih1, Whh1};
    for (int m = 0; m < 3; m++) {
        const float4* W4 = (const float4*)Wm[m];
        for (int i = tid; i < 24 * 256; i += 384) {
            int r = i >> 8, cu = i & 255;
            int grow = (r >> 3) * NH + j0 + (r & 7);
            float4 v = W4[grow * 256 + cu];
            int base = (cu * 2) ^ ((r & 7) << 2);
            __half2* d = &sW[m * 12288 + r * 512 + base];
            d[0] = __floats2half2_rn(v.x, v.y);
            d[1] = __floats2half2_rn(v.z, v.w);
        }
    }
    const float* Bm[3] = {bhh0, bih1, bhh1};
    if (tid < 72) {
        int m = tid / 24, r = tid % 24;
        sBias[tid] = Bm[m][(r >> 3) * NH + j0 + (r & 7)];
    }
    if (tid < 256) {
        float a = encH[b * NH + j0 + jj], c2 = encH[b * NH + j0 + jj + 1];
        sH0f[b * 8 + jj] = a; sH0f[b * 8 + jj + 1] = c2;
        sH1f[b * 8 + jj] = a; sH1f[b * 8 + jj + 1] = c2;
        __half2 hp = __floats2half2_rn(a, c2);
        g_h0[1][b * 512 + ((j0 + jj) >> 1)] = hp;   // h0^{-1}
        g_h1[0][b * 512 + ((j0 + jj) >> 1)] = hp;   // h1^{-2} dummy
        g_h1[1][b * 512 + ((j0 + jj) >> 1)] = hp;   // h1^{-1}
    }
    bar_arrive(&g_bari);
    bar_wait(&g_bari, GCTA);

    for (int i = 0; i <= NT; i++) {
        __half2 pg0, pg1, pg2;
        if (i < NT && tid < 256) {
            size_t gi = ((size_t)i * NB + b) * 1536 + ((j0 + jj) >> 1);
            pg0 = g_gi0[gi]; pg1 = g_gi0[gi + 512]; pg2 = g_gi0[gi + 1024];
        }
        if (i >= 1) {
            bar_wait(&g_bar0, (unsigned)i * GCTA);   // h0^{i-1}
            bar_wait(&g_bar1, (unsigned)i * GCTA);   // h1^{i-2}
        }
        const uint4* A1 = (const uint4*)g_h0[(i + 1) & 1];
        const uint4* A2 = (const uint4*)g_h1[i & 1];

        auto issue = [&](int p, int buf) {
            if (tid < 256) {
#pragma unroll
                for (int q = 0; q < 4; q++) {
                    int idx = tid * 2 + (q & 1);
                    int r = idx >> 3, cu = idx & 7;
                    unsigned base = (unsigned)((buf * 2048 + r * 32 +
                                    ((cu * 4) ^ ((r & 7) << 2))) * 4);
                    const uint4* src = ((q < 2) ? A1 : A2) + (size_t)r * 128 + p * 8 + cu;
                    cp16(((q < 2) ? sA1u : sA2u) + base, src);
                }
            }
            cp_commit();
        };

        float cc[3][2][4] = {};
        issue(0, 0); issue(1, 1);
        const __half2* sAbase = (msel == 2) ? sA2 : sA1;
        const __half2* wb = sW + msel * 12288 + brow * 512;
        const int s0 = kh * 2;
        const int ca = 8 * s0 + 4 * alo;

        for (int p = 0; p < 16; p++) {
            if (p < 15) cp_wait<1>(); else cp_wait<0>();
            __syncthreads();
            if (p + 2 < 16) issue(p + 2, (p + 2) % 3);
            const __half2* aB = sAbase + (p % 3) * 2048;
            unsigned a00, a01, a02, a03, e00, e01, e02, e03;
            unsigned a10, a11, a12, a13, e10, e11, e12, e13;
            ldsm4(a00, a01, a02, a03, aB + aoff0 + (ca ^ asw));
            ldsm4(e00, e01, e02, e03, aB + aoff0 + ((ca + 8) ^ asw));
            ldsm4(a10, a11, a12, a13, aB + aoff1 + (ca ^ asw));
            ldsm4(e10, e11, e12, e13, aB + aoff1 + ((ca + 8) ^ asw));
            int g = p * 4 + s0;
            int cb = 8 * g + 4 * blo;
            unsigned b0[4], b1[4], b2[4];
            ldsm4(b0[0], b0[1], b0[2], b0[3], wb + (cb ^ bsw));
            ldsm4(b1[0], b1[1], b1[2], b1[3], wb + 4096 + (cb ^ bsw));
            ldsm4(b2[0], b2[1], b2[2], b2[3], wb + 8192 + (cb ^ bsw));
            // k-step s0
            mma16816(cc[0][0], a00, a01, a02, a03, b0[0], b0[1]);
            mma16816(cc[1][0], a00, a01, a02, a03, b1[0], b1[1]);
            mma16816(cc[2][0], a00, a01, a02, a03, b2[0], b2[1]);
            mma16816(cc[0][1], a10, a11, a12, a13, b0[0], b0[1]);
            mma16816(cc[1][1], a10, a11, a12, a13, b1[0], b1[1]);
            mma16816(cc[2][1], a10, a11, a12, a13, b2[0], b2[1]);
            // k-step s0+1
            mma16816(cc[0][0], e00, e01, e02, e03, b0[2], b0[3]);
            mma16816(cc[1][0], e00, e01, e02, e03, b1[2], b1[3]);
            mma16816(cc[2][0], e00, e01, e02, e03, b2[2], b2[3]);
            mma16816(cc[0][1], e10, e11, e12, e13, b0[2], b0[3]);
            mma16816(cc[1][1], e10, e11, e12, e13, b1[2], b1[3]);
            mma16816(cc[2][1], e10, e11, e12, e13, b2[2], b2[3]);
        }
        __syncthreads();

        // epilogue: 2-phase k-half reduction in place
        float* dst = sPre + msel * 1536;
        int nc = 2 * tg;
        if (kh == 1) {
#pragma unroll
            for (int g = 0; g < 3; g++)
#pragma unroll
                for (int t = 0; t < 2; t++) {
                    int r0 = mt * 32 + t * 16 + gID;
                    *(float2*)&dst[r0 * 24 + g * 8 + nc]       = make_float2(cc[g][t][0], cc[g][t][1]);
                    *(float2*)&dst[(r0 + 8) * 24 + g * 8 + nc] = make_float2(cc[g][t][2], cc[g][t][3]);
                }
        }
        __syncthreads();
        if (kh == 0) {
#pragma unroll
            for (int g = 0; g < 3; g++)
#pragma unroll
                for (int t = 0; t < 2; t++) {
                    int r0 = mt * 32 + t * 16 + gID;
                    float2 p0 = *(float2*)&dst[r0 * 24 + g * 8 + nc];
                    float2 p1 = *(float2*)&dst[(r0 + 8) * 24 + g * 8 + nc];
                    *(float2*)&dst[r0 * 24 + g * 8 + nc] =
                        make_float2(cc[g][t][0] + p0.x, cc[g][t][1] + p0.y);
                    *(float2*)&dst[(r0 + 8) * 24 + g * 8 + nc] =
                        make_float2(cc[g][t][2] + p1.x, cc[g][t][3] + p1.y);
                }
        }
        __syncthreads();

        // elementwise: L0 step i, L1 step i-1
        if (tid < 256) {
            if (i < NT) {
                float gir[2] = {__low2float(pg0), __high2float(pg0)};
                float giz[2] = {__low2float(pg1), __high2float(pg1)};
                float gin[2] = {__low2float(pg2), __high2float(pg2)};
                float h0n[2];
#pragma unroll
                for (int d = 0; d < 2; d++) {
                    int j = jj + d;
                    float r = sigm(gir[d] + sPre[b * 24 + j]      + sBias[j]);
                    float z = sigm(giz[d] + sPre[b * 24 + 8 + j]  + sBias[8 + j]);
                    float n = tanhf(gin[d] + r * (sPre[b * 24 + 16 + j] + sBias[16 + j]));
                    h0n[d] = (1.0f - z) * n + z * sH0f[b * 8 + j];
                }
                sH0f[b * 8 + jj] = h0n[0]; sH0f[b * 8 + jj + 1] = h0n[1];
                g_h0[i & 1][b * 512 + ((j0 + jj) >> 1)] = __floats2half2_rn(h0n[0], h0n[1]);
            }
            if (i >= 1) {
                int t = i - 1;
                float h1n[2];
#pragma unroll
                for (int d = 0; d < 2; d++) {
                    int j = jj + d;
                    float r = sigm(sPre[1536 + b * 24 + j]     + sBias[24 + j] +
                                   sPre[3072 + b * 24 + j]     + sBias[48 + j]);
                    float z = sigm(sPre[1536 + b * 24 + 8 + j] + sBias[32 + j] +
                                   sPre[3072 + b * 24 + 8 + j] + sBias[56 + j]);
                    float n = tanhf(sPre[1536 + b * 24 + 16 + j] + sBias[40 + j] +
                                    r * (sPre[3072 + b * 24 + 16 + j] + sBias[64 + j]));
                    h1n[d] = (1.0f - z) * n + z * sH1f[b * 8 + j];
                }
                sH1f[b * 8 + jj] = h1n[0]; sH1f[b * 8 + jj + 1] = h1n[1];
                g_h1[(i + 1) & 1][b * 512 + ((j0 + jj) >> 1)] = __floats2half2_rn(h1n[0], h1n[1]);
                *(float2*)&out[((size_t)b * NT + t) * NH + j0 + jj] = make_float2(h1n[0], h1n[1]);
                if (hasFinal && t == NT - 1) {
                    float* o2 = out + (size_t)NB * NT * NH;
                    *(float2*)&o2[b * NH + j0 + jj] = make_float2(h1n[0], h1n[1]);
                }
            }
        }
        // publish both barriers with one block sync
        __syncthreads();
        if (threadIdx.x == 0 && i < NT) {
            __threadfence();
            atomicAdd(&g_bar0, 1u);
            atomicAdd(&g_bar1, 1u);
        }
    }
}

extern "C" void kernel_launch(void* const* d_in, const int* in_sizes, int n_in,
                              void* d_out, int out_size) {
    const float* x    = (const float*)d_in[0];
    const float* encH = (const float*)d_in[2];
    const float* Wih0 = (const float*)d_in[3];
    const float* Whh0 = (const float*)d_in[4];
    const float* bih0 = (const float*)d_in[5];
    const float* bhh0 = (const float*)d_in[6];
    const float* Wih1 = (const float*)d_in[7];
    const float* Whh1 = (const float*)d_in[8];
    const float* bih1 = (const float*)d_in[9];
    const float* bhh1 = (const float*)d_in[10];
    float* out = (float*)d_out;
    int hasFinal = (out_size >= NB * NT * NH + NB * NH) ? 1 : 0;

    cudaFuncSetAttribute(k_gru, cudaFuncAttributeMaxDynamicSharedMemorySize, SMEM_BYTES);

    k_cvt_x<<<16384, 256>>>((const float4*)x);
    k_cvt_w<<<1536, 256>>>((const float4*)Wih0);
    dim3 g1(48, 512);
    k_gi0<<<g1, 256>>>(bih0);
    k_gru<<<GCTA, 384, SMEM_BYTES>>>(out, Whh0, Wih1, Whh1,
                                     bhh0, bih1, bhh1, encH, hasFinal);
}

// round 11
// speedup vs baseline: 2.2211x; 1.0697x over previous
#include <cuda_runtime.h>
#include <cuda_fp16.h>
#include <math.h>

#define NB   64
#define NT   512
#define NIN  512
#define NH   1024
#define GCTA 128

__device__ __half2  g_x16[NB * NT * NIN / 2];
__device__ __half2  g_w16[3 * NH * NIN / 2];
__device__ __half2  g_gi0[(size_t)NB * NT * 3 * NH / 2];  // [t][b][3072] fp16, +bias
__device__ __half2  g_h0[2][NB * NH / 2];
__device__ __half2  g_h1[2][NB * NH / 2];
__device__ unsigned g_bar0, g_bari;

__device__ __forceinline__ float sigm(float x) { return 1.0f / (1.0f + __expf(-x)); }

__device__ __forceinline__ void mma16816(float* c, unsigned a0, unsigned a1,
                                         unsigned a2, unsigned a3,
                                         unsigned b0, unsigned b1) {
    asm volatile(
        "mma.sync.aligned.m16n8k16.row.col.f32.f16.f16.f32 "
        "{%0,%1,%2,%3},{%4,%5,%6,%7},{%8,%9},{%0,%1,%2,%3};\n"
        : "+f"(c[0]), "+f"(c[1]), "+f"(c[2]), "+f"(c[3])
        : "r"(a0), "r"(a1), "r"(a2), "r"(a3), "r"(b0), "r"(b1));
}

__device__ __forceinline__ void ldsm4(unsigned& r0, unsigned& r1,
                                      unsigned& r2, unsigned& r3,
                                      const __half2* p) {
    unsigned a = (unsigned)__cvta_generic_to_shared(p);
    asm volatile("ldmatrix.sync.aligned.m8n8.x4.shared.b16 {%0,%1,%2,%3}, [%4];"
                 : "=r"(r0), "=r"(r1), "=r"(r2), "=r"(r3) : "r"(a));
}

__device__ __forceinline__ void cp16(unsigned dst, const void* src) {
    asm volatile("cp.async.cg.shared.global [%0], [%1], 16;" :: "r"(dst), "l"(src));
}
__device__ __forceinline__ void cp_commit() { asm volatile("cp.async.commit_group;"); }
template <int N> __device__ __forceinline__ void cp_wait() {
    asm volatile("cp.async.wait_group %0;" :: "n"(N));
}

__device__ __forceinline__ void bar_arrive1(unsigned* bar) {
    __syncthreads();
    if (threadIdx.x == 0) { __threadfence(); atomicAdd(bar, 1u); }
}
__device__ __forceinline__ void bar_wait(unsigned* bar, unsigned target) {
    if (threadIdx.x == 0) {
        unsigned v;
        do {
            asm volatile("ld.global.acquire.gpu.u32 %0, [%1];"
                         : "=r"(v) : "l"(bar) : "memory");
        } while (v < target);
    }
    __syncthreads();
}

__global__ void k_cvt_x(const float4* __restrict__ x) {
    int i = blockIdx.x * 256 + threadIdx.x;
    if (i == 0) { g_bar0 = 0; g_bari = 0; }
    float4 v = x[i];
    g_x16[i * 2]     = __floats2half2_rn(v.x, v.y);
    g_x16[i * 2 + 1] = __floats2half2_rn(v.z, v.w);
}
__global__ void k_cvt_w(const float4* __restrict__ w) {
    int i = blockIdx.x * 256 + threadIdx.x;
    float4 v = w[i];
    g_w16[i * 2]     = __floats2half2_rn(v.x, v.y);
    g_w16[i * 2 + 1] = __floats2half2_rn(v.z, v.w);
}

// ---- phase A: gi0 = x @ Wih0^T + bih0 ----
__global__ void __launch_bounds__(256) k_gi0(const float* __restrict__ bih0) {
    __shared__ __half2 sA[64 * 32];
    __shared__ __half2 sB[64 * 32];
    const int tid = threadIdx.x, wid = tid >> 5, lane = tid & 31;
    const int wm = wid & 3, wn = wid >> 2, gID = lane >> 2, tg = lane & 3;
    const int m0 = blockIdx.y * 64, n0 = blockIdx.x * 64;
    const uint4* A4 = (const uint4*)g_x16;
    const uint4* B4 = (const uint4*)g_w16;
    const int swz = gID << 2;
    float c[4][4] = {};

    for (int p = 0; p < 8; p++) {
        __syncthreads();
#pragma unroll
        for (int rep = 0; rep < 2; rep++) {
            int idx = rep * 256 + tid, r = idx >> 3, cu = idx & 7;
            int base = (cu * 4) ^ ((r & 7) << 2);
            *(uint4*)&sA[r * 32 + base] = A4[(m0 + r) * 64 + p * 8 + cu];
            *(uint4*)&sB[r * 32 + base] = B4[(n0 + r) * 64 + p * 8 + cu];
        }
        __syncthreads();
#pragma unroll
        for (int ks = 0; ks < 4; ks++) {
            int col = ks * 8 + tg;
            int ra0 = (wm * 16 + gID) * 32, ra1 = ra0 + 8 * 32;
            unsigned a0 = *(const unsigned*)&sA[ra0 + (col ^ swz)];
            unsigned a1 = *(const unsigned*)&sA[ra1 + (col ^ swz)];
            unsigned a2 = *(const unsigned*)&sA[ra0 + ((col + 4) ^ swz)];
            unsigned a3 = *(const unsigned*)&sA[ra1 + ((col + 4) ^ swz)];
#pragma unroll
            for (int nt = 0; nt < 4; nt++) {
                int rb = (wn * 32 + nt * 8 + gID) * 32;
                unsigned b0 = *(const unsigned*)&sB[rb + (col ^ swz)];
                unsigned b1 = *(const unsigned*)&sB[rb + ((col + 4) ^ swz)];
                mma16816(c[nt], a0, a1, a2, a3, b0, b1);
            }
        }
    }
    int mrow = m0 + wm * 16 + gID;
#pragma unroll
    for (int nt = 0; nt < 4; nt++) {
        int nc = n0 + wn * 32 + nt * 8 + tg * 2;
        float b0 = bih0[nc], b1 = bih0[nc + 1];
        int bA = mrow >> 9, tA = mrow & 511;
        g_gi0[((size_t)tA * NB + bA) * 1536 + (nc >> 1)] =
            __floats2half2_rn(c[nt][0] + b0, c[nt][1] + b1);
        int m2 = mrow + 8, bB = m2 >> 9, tB = m2 & 511;
        g_gi0[((size_t)tB * NB + bB) * 1536 + (nc >> 1)] =
            __floats2half2_rn(c[nt][2] + b0, c[nt][3] + b1);
    }
}

// ---- persistent recurrence: 12 uniform warps, depth-3 panel pipeline ----
// smem (h2 units): sW 36864 | sA1 4x2048 @36864 | sA2 4x2048 @45056 |
//   state @53248: sH0f 512f, sH1f 512f, sBias 72f. sPre overlays sA1.
#define SMEM_BYTES (53248 * 4 + 4384)

__global__ void __launch_bounds__(384, 1) k_gru(
    float* __restrict__ out,
    const float* __restrict__ Whh0, const float* __restrict__ Wih1,
    const float* __restrict__ Whh1,
    const float* __restrict__ bhh0, const float* __restrict__ bih1,
    const float* __restrict__ bhh1,
    const float* __restrict__ encH, int hasFinal) {
    extern __shared__ __align__(16) __half2 smem[];
    __half2* sW   = smem;                  // 36864 h2
    __half2* sA1  = smem + 36864;          // 4 x 2048 h2
    __half2* sA2  = smem + 45056;          // 4 x 2048 h2
    float*   sPre = (float*)(smem + 36864);       // OVERLAY on sA1 (epilogue only)
    float*   sH0f = (float*)(smem + 53248);
    float*   sH1f = sH0f + 512;
    float*   sBias = sH1f + 512;

    const int tid = threadIdx.x, wid = tid >> 5, lane = tid & 31;
    const int msel = wid >> 2;              // 0,1,2 : Whh0 / Wih1 / Whh1
    const int mt   = wid & 1;               // m-half
    const int kh   = (wid >> 1) & 1;        // k-half within panel
    const int gID = lane >> 2, tg = lane & 3;
    const int j0 = blockIdx.x * 8;
    const int b = tid >> 2, jj = (tid & 3) * 2;   // valid tid<256
    const int l15 = lane & 15, alo = lane >> 4;
    const int asw = (lane & 7) << 2;
    const int aoff0 = (mt * 32 + l15) * 32;
    const int aoff1 = aoff0 + 16 * 32;
    const int brow = lane & 7, bsw = brow << 2, blo = lane >> 3;
    const unsigned sA1u = (unsigned)__cvta_generic_to_shared(sA1);
    const unsigned sA2u = (unsigned)__cvta_generic_to_shared(sA2);

    const float* Wm[3] = {Whh0, Wih1, Whh1};
    for (int m = 0; m < 3; m++) {
        const float4* W4 = (const float4*)Wm[m];
        for (int i = tid; i < 24 * 256; i += 384) {
            int r = i >> 8, cu = i & 255;
            int grow = (r >> 3) * NH + j0 + (r & 7);
            float4 v = W4[grow * 256 + cu];
            int base = (cu * 2) ^ ((r & 7) << 2);
            __half2* d = &sW[m * 12288 + r * 512 + base];
            d[0] = __floats2half2_rn(v.x, v.y);
            d[1] = __floats2half2_rn(v.z, v.w);
        }
    }
    const float* Bm[3] = {bhh0, bih1, bhh1};
    if (tid < 72) {
        int m = tid / 24, r = tid % 24;
        sBias[tid] = Bm[m][(r >> 3) * NH + j0 + (r & 7)];
    }
    if (tid < 256) {
        float a = encH[b * NH + j0 + jj], c2 = encH[b * NH + j0 + jj + 1];
        sH0f[b * 8 + jj] = a; sH0f[b * 8 + jj + 1] = c2;
        sH1f[b * 8 + jj] = a; sH1f[b * 8 + jj + 1] = c2;
        __half2 hp = __floats2half2_rn(a, c2);
        g_h0[1][b * 512 + ((j0 + jj) >> 1)] = hp;   // h0^{-1}
        g_h1[0][b * 512 + ((j0 + jj) >> 1)] = hp;   // h1^{-2} dummy
        g_h1[1][b * 512 + ((j0 + jj) >> 1)] = hp;   // h1^{-1}
    }
    bar_arrive1(&g_bari);
    bar_wait(&g_bari, GCTA);

    for (int i = 0; i <= NT; i++) {
        __half2 pg0, pg1, pg2;
        if (i < NT && tid < 256) {
            size_t gi = ((size_t)i * NB + b) * 1536 + ((j0 + jj) >> 1);
            pg0 = g_gi0[gi]; pg1 = g_gi0[gi + 512]; pg2 = g_gi0[gi + 1024];
        }
        if (i >= 1) bar_wait(&g_bar0, (unsigned)i * GCTA);  // h0^{i-1}, h1^{i-2}
        const uint4* A1 = (const uint4*)g_h0[(i + 1) & 1];
        const uint4* A2 = (const uint4*)g_h1[i & 1];

        auto issue = [&](int p, int buf) {
            if (tid < 256) {
#pragma unroll
                for (int q = 0; q < 4; q++) {
                    int idx = tid * 2 + (q & 1);
                    int r = idx >> 3, cu = idx & 7;
                    unsigned base = (unsigned)((buf * 2048 + r * 32 +
                                    ((cu * 4) ^ ((r & 7) << 2))) * 4);
                    const uint4* src = ((q < 2) ? A1 : A2) + (size_t)r * 128 + p * 8 + cu;
                    cp16(((q < 2) ? sA1u : sA2u) + base, src);
                }
            }
            cp_commit();
        };

        float cc[3][2][4] = {};
        issue(0, 0); issue(1, 1); issue(2, 2);
        const __half2* sAbase = (msel == 2) ? sA2 : sA1;
        const __half2* wb = sW + msel * 12288 + brow * 512;
        const int s0 = kh * 2;
        const int ca = 8 * s0 + 4 * alo;

        for (int p = 0; p < 16; p++) {
            if (p < 14) cp_wait<2>();
            else if (p == 14) cp_wait<1>();
            else cp_wait<0>();
            __syncthreads();
            if (p + 3 < 16) issue(p + 3, (p + 3) & 3);
            const __half2* aB = sAbase + (p & 3) * 2048;
            unsigned a00, a01, a02, a03, e00, e01, e02, e03;
            unsigned a10, a11, a12, a13, e10, e11, e12, e13;
            ldsm4(a00, a01, a02, a03, aB + aoff0 + (ca ^ asw));
            ldsm4(e00, e01, e02, e03, aB + aoff0 + ((ca + 8) ^ asw));
            ldsm4(a10, a11, a12, a13, aB + aoff1 + (ca ^ asw));
            ldsm4(e10, e11, e12, e13, aB + aoff1 + ((ca + 8) ^ asw));
            int g = p * 4 + s0;
            int cb = 8 * g + 4 * blo;
            unsigned b0[4], b1[4], b2[4];
            ldsm4(b0[0], b0[1], b0[2], b0[3], wb + (cb ^ bsw));
            ldsm4(b1[0], b1[1], b1[2], b1[3], wb + 4096 + (cb ^ bsw));
            ldsm4(b2[0], b2[1], b2[2], b2[3], wb + 8192 + (cb ^ bsw));
            mma16816(cc[0][0], a00, a01, a02, a03, b0[0], b0[1]);
            mma16816(cc[1][0], a00, a01, a02, a03, b1[0], b1[1]);
            mma16816(cc[2][0], a00, a01, a02, a03, b2[0], b2[1]);
            mma16816(cc[0][1], a10, a11, a12, a13, b0[0], b0[1]);
            mma16816(cc[1][1], a10, a11, a12, a13, b1[0], b1[1]);
            mma16816(cc[2][1], a10, a11, a12, a13, b2[0], b2[1]);
            mma16816(cc[0][0], e00, e01, e02, e03, b0[2], b0[3]);
            mma16816(cc[1][0], e00, e01, e02, e03, b1[2], b1[3]);
            mma16816(cc[2][0], e00, e01, e02, e03, b2[2], b2[3]);
            mma16816(cc[0][1], e10, e11, e12, e13, b0[2], b0[3]);
            mma16816(cc[1][1], e10, e11, e12, e13, b1[2], b1[3]);
            mma16816(cc[2][1], e10, e11, e12, e13, b2[2], b2[3]);
        }
        __syncthreads();

        // epilogue: 2-phase k-half reduction into sPre (overlay; panels drained)
        float* dst = sPre + msel * 1536;
        int nc = 2 * tg;
        if (kh == 1) {
#pragma unroll
            for (int g = 0; g < 3; g++)
#pragma unroll
                for (int t = 0; t < 2; t++) {
                    int r0 = mt * 32 + t * 16 + gID;
                    *(float2*)&dst[r0 * 24 + g * 8 + nc]       = make_float2(cc[g][t][0], cc[g][t][1]);
                    *(float2*)&dst[(r0 + 8) * 24 + g * 8 + nc] = make_float2(cc[g][t][2], cc[g][t][3]);
                }
        }
        __syncthreads();
        if (kh == 0) {
#pragma unroll
            for (int g = 0; g < 3; g++)
#pragma unroll
                for (int t = 0; t < 2; t++) {
                    int r0 = mt * 32 + t * 16 + gID;
                    float2 p0 = *(float2*)&dst[r0 * 24 + g * 8 + nc];
                    float2 p1 = *(float2*)&dst[(r0 + 8) * 24 + g * 8 + nc];
                    *(float2*)&dst[r0 * 24 + g * 8 + nc] =
                        make_float2(cc[g][t][0] + p0.x, cc[g][t][1] + p0.y);
                    *(float2*)&dst[(r0 + 8) * 24 + g * 8 + nc] =
                        make_float2(cc[g][t][2] + p1.x, cc[g][t][3] + p1.y);
                }
        }
        __syncthreads();

        // elementwise: L0 step i, L1 step i-1
        if (tid < 256) {
            if (i < NT) {
                float gir[2] = {__low2float(pg0), __high2float(pg0)};
                float giz[2] = {__low2float(pg1), __high2float(pg1)};
                float gin[2] = {__low2float(pg2), __high2float(pg2)};
                float h0n[2];
#pragma unroll
                for (int d = 0; d < 2; d++) {
                    int j = jj + d;
                    float r = sigm(gir[d] + sPre[b * 24 + j]      + sBias[j]);
                    float z = sigm(giz[d] + sPre[b * 24 + 8 + j]  + sBias[8 + j]);
                    float n = tanhf(gin[d] + r * (sPre[b * 24 + 16 + j] + sBias[16 + j]));
                    h0n[d] = (1.0f - z) * n + z * sH0f[b * 8 + j];
                }
                sH0f[b * 8 + jj] = h0n[0]; sH0f[b * 8 + jj + 1] = h0n[1];
                g_h0[i & 1][b * 512 + ((j0 + jj) >> 1)] = __floats2half2_rn(h0n[0], h0n[1]);
            }
            if (i >= 1) {
                int t = i - 1;
                float h1n[2];
#pragma unroll
                for (int d = 0; d < 2; d++) {
                    int j = jj + d;
                    float r = sigm(sPre[1536 + b * 24 + j]     + sBias[24 + j] +
                                   sPre[3072 + b * 24 + j]     + sBias[48 + j]);
                    float z = sigm(sPre[1536 + b * 24 + 8 + j] + sBias[32 + j] +
                                   sPre[3072 + b * 24 + 8 + j] + sBias[56 + j]);
                    float n = tanhf(sPre[1536 + b * 24 + 16 + j] + sBias[40 + j] +
                                    r * (sPre[3072 + b * 24 + 16 + j] + sBias[64 + j]));
                    h1n[d] = (1.0f - z) * n + z * sH1f[b * 8 + j];
                }
                sH1f[b * 8 + jj] = h1n[0]; sH1f[b * 8 + jj + 1] = h1n[1];
                g_h1[(i + 1) & 1][b * 512 + ((j0 + jj) >> 1)] = __floats2half2_rn(h1n[0], h1n[1]);
                *(float2*)&out[((size_t)b * NT + t) * NH + j0 + jj] = make_float2(h1n[0], h1n[1]);
                if (hasFinal && t == NT - 1) {
                    float* o2 = out + (size_t)NB * NT * NH;
                    *(float2*)&o2[b * NH + j0 + jj] = make_float2(h1n[0], h1n[1]);
                }
            }
        }
        __syncthreads();
        if (threadIdx.x == 0 && i < NT) {
            __threadfence();
            atomicAdd(&g_bar0, 1u);
        }
    }
}

extern "C" void kernel_launch(void* const* d_in, const int* in_sizes, int n_in,
                              void* d_out, int out_size) {
    const float* x    = (const float*)d_in[0];
    const float* encH = (const float*)d_in[2];
    const float* Wih0 = (const float*)d_in[3];
    const float* Whh0 = (const float*)d_in[4];
    const float* bih0 = (const float*)d_in[5];
    const float* bhh0 = (const float*)d_in[6];
    const float* Wih1 = (const float*)d_in[7];
    const float* Whh1 = (const float*)d_in[8];
    const float* bih1 = (const float*)d_in[9];
    const float* bhh1 = (const float*)d_in[10];
    float* out = (float*)d_out;
    int hasFinal = (out_size >= NB * NT * NH + NB * NH) ? 1 : 0;

    cudaFuncSetAttribute(k_gru, cudaFuncAttributeMaxDynamicSharedMemorySize, SMEM_BYTES);

    k_cvt_x<<<16384, 256>>>((const float4*)x);
    k_cvt_w<<<1536, 256>>>((const float4*)Wih0);
    dim3 g1(48, 512);
    k_gi0<<<g1, 256>>>(bih0);
    k_gru<<<GCTA, 384, SMEM_BYTES>>>(out, Whh0, Wih1, Whh1,
                                     bhh0, bih1, bhh1, encH, hasFinal);
}